// round 12
// baseline (speedup 1.0000x reference)
#include <cuda_runtime.h>
#include <cuda_bf16.h>
#include <cstdint>

// ---------------------------------------------------------------------------
// LIF layer: cur = X @ W^T + b via bf16x3-split GEMM on mma.sync (HMMA).
// R12: K1 and K2 fused into ONE kernel with heterogeneous CTAs:
//      blockIdx.x&1==0 -> main path (a0*b0, chain-4 + lo/hi drain, writes
//      g_cur = main+bias); ==1 -> small path (5 products, writes g_cur2).
//      Alternating dispatch mixes drain-heavy and mma-dense CTAs per SM,
//      overlapping the FMA and tensor pipes. Scan sums g_cur + g_cur2.
// ---------------------------------------------------------------------------

constexpr int T_DIM  = 64;
constexpr int B_DIM  = 128;
constexpr int IN_DIM = 2048;
constexpr int OUT_DIM = 2048;
constexpr int M_DIM  = T_DIM * B_DIM;          // 8192
constexpr float THR_V   = 1.0f;
constexpr float DECAY_V = 0.60653065971263342f; // exp(-1/2) rounded to fp32

// ------------------------------ scratch -----------------------------------
__device__ float g_cur [(size_t)M_DIM * OUT_DIM];                // 64 MB
__device__ float g_cur2[(size_t)M_DIM * OUT_DIM];                // 64 MB
__device__ __nv_bfloat16 g_A0[(size_t)M_DIM * IN_DIM];           // 32 MB each
__device__ __nv_bfloat16 g_A1[(size_t)M_DIM * IN_DIM];
__device__ __nv_bfloat16 g_A2[(size_t)M_DIM * IN_DIM];
__device__ __nv_bfloat16 g_B0[(size_t)OUT_DIM * IN_DIM];         // 8 MB each
__device__ __nv_bfloat16 g_B1[(size_t)OUT_DIM * IN_DIM];
__device__ __nv_bfloat16 g_B2[(size_t)OUT_DIM * IN_DIM];

// ------------------------------ helpers -----------------------------------
__device__ __forceinline__ uint32_t smem_u32(const void* p) {
    uint32_t a;
    asm("{ .reg .u64 t; cvta.to.shared.u64 t, %1; cvt.u32.u64 %0, t; }"
        : "=r"(a) : "l"(p));
    return a;
}

#define SW128(o) ((o) ^ (((o) >> 3) & 0x70))

__device__ __forceinline__ void ldmx4(uint32_t* r, uint32_t addr) {
    asm volatile("ldmatrix.sync.aligned.m8n8.x4.shared.b16 {%0,%1,%2,%3}, [%4];"
                 : "=r"(r[0]), "=r"(r[1]), "=r"(r[2]), "=r"(r[3]) : "r"(addr));
}
// chained accumulate: d += a*b
__device__ __forceinline__ void mma16816(float* d, const uint32_t* a,
                                         const uint32_t* b) {
    asm volatile(
        "mma.sync.aligned.m16n8k16.row.col.f32.bf16.bf16.f32 "
        "{%0,%1,%2,%3}, {%4,%5,%6,%7}, {%8,%9}, {%0,%1,%2,%3};"
        : "+f"(d[0]), "+f"(d[1]), "+f"(d[2]), "+f"(d[3])
        : "r"(a[0]), "r"(a[1]), "r"(a[2]), "r"(a[3]), "r"(b[0]), "r"(b[1]));
}
// zero-C form: d = a*b
__device__ __forceinline__ void mma16816_z(float* d, const uint32_t* a,
                                           const uint32_t* b) {
    asm volatile(
        "mma.sync.aligned.m16n8k16.row.col.f32.bf16.bf16.f32 "
        "{%0,%1,%2,%3}, {%4,%5,%6,%7}, {%8,%9}, {%10,%11,%12,%13};"
        : "=f"(d[0]), "=f"(d[1]), "=f"(d[2]), "=f"(d[3])
        : "r"(a[0]), "r"(a[1]), "r"(a[2]), "r"(a[3]), "r"(b[0]), "r"(b[1]),
          "f"(0.0f), "f"(0.0f), "f"(0.0f), "f"(0.0f));
}

// ------------------------- split fp32 -> 3x bf16 ---------------------------
__device__ __forceinline__ void split3(float v, __nv_bfloat16& h0,
                                       __nv_bfloat16& h1, __nv_bfloat16& h2) {
    h0 = __float2bfloat16(v);
    float r1 = v - __bfloat162float(h0);
    h1 = __float2bfloat16(r1);
    float r2 = r1 - __bfloat162float(h1);
    h2 = __float2bfloat16(r2);
}

__global__ __launch_bounds__(256) void split_x_kernel(const float* __restrict__ src)
{
    int i = blockIdx.x * blockDim.x + threadIdx.x;
    float4 a = reinterpret_cast<const float4*>(src)[i];
    float v[4] = {a.x, a.y, a.z, a.w};
    __nv_bfloat16 h0[4], h1[4], h2[4];
#pragma unroll
    for (int j = 0; j < 4; j++) split3(v[j], h0[j], h1[j], h2[j]);
    __nv_bfloat162 p;
    p = {h0[0], h0[1]}; reinterpret_cast<__nv_bfloat162*>(g_A0)[2*i  ] = p;
    p = {h0[2], h0[3]}; reinterpret_cast<__nv_bfloat162*>(g_A0)[2*i+1] = p;
    p = {h1[0], h1[1]}; reinterpret_cast<__nv_bfloat162*>(g_A1)[2*i  ] = p;
    p = {h1[2], h1[3]}; reinterpret_cast<__nv_bfloat162*>(g_A1)[2*i+1] = p;
    p = {h2[0], h2[1]}; reinterpret_cast<__nv_bfloat162*>(g_A2)[2*i  ] = p;
    p = {h2[2], h2[3]}; reinterpret_cast<__nv_bfloat162*>(g_A2)[2*i+1] = p;
}

__global__ __launch_bounds__(256) void split_w_kernel(const float* __restrict__ src)
{
    int i = blockIdx.x * blockDim.x + threadIdx.x;
    float4 a = reinterpret_cast<const float4*>(src)[i];
    float v[4] = {a.x, a.y, a.z, a.w};
    __nv_bfloat16 h0[4], h1[4], h2[4];
#pragma unroll
    for (int j = 0; j < 4; j++) split3(v[j], h0[j], h1[j], h2[j]);
    __nv_bfloat162 p;
    p = {h0[0], h0[1]}; reinterpret_cast<__nv_bfloat162*>(g_B0)[2*i  ] = p;
    p = {h0[2], h0[3]}; reinterpret_cast<__nv_bfloat162*>(g_B0)[2*i+1] = p;
    p = {h1[0], h1[1]}; reinterpret_cast<__nv_bfloat162*>(g_B1)[2*i  ] = p;
    p = {h1[2], h1[3]}; reinterpret_cast<__nv_bfloat162*>(g_B1)[2*i+1] = p;
    p = {h2[0], h2[1]}; reinterpret_cast<__nv_bfloat162*>(g_B2)[2*i  ] = p;
    p = {h2[2], h2[3]}; reinterpret_cast<__nv_bfloat162*>(g_B2)[2*i+1] = p;
}

// ------------------------------ common dims --------------------------------
constexpr int BM = 128, BN = 64, BK = 64;
constexpr int NST = IN_DIM / BK;              // 32 ktiles
constexpr int TILE_A  = 128 * 128;            // 16 KB A tile (128 rows)
constexpr int TILE_BB = 64 * 128;             // 8 KB B tile (64 rows)
constexpr int F_SMEM = 3 * TILE_A + 3 * TILE_BB;  // 73728 (worst path: small)

// ============================ fused GEMM ====================================
// grid (64, 64): bx&1==0 -> main path, ==1 -> small path; bn = (bx>>1)*64.
// Both paths: 256 threads = 8 warps (4 wm x 2 wn), warp tile 32x32.
__global__ __launch_bounds__(256, 2)
void gemm_fused_kernel(const float* __restrict__ bias)
{
    extern __shared__ char smem[];
    const uint32_t sb = smem_u32(smem);
    const int tid  = threadIdx.x;
    const int wid  = tid >> 5;
    const int lane = tid & 31;
    const int bm = blockIdx.y * BM;
    const int bn = (blockIdx.x >> 1) * BN;
    const int warp_m = wid & 3;      // 0..3
    const int warp_n = wid >> 2;     // 0..1
    const int mi = lane >> 3, r8 = lane & 7;
    const int qr = lane >> 2;
    const int qc = (lane & 3) * 2;

    if ((blockIdx.x & 1) == 0) {
        // ==================== main path: a0*b0 + bias -> g_cur =============
        const __nv_bfloat16* Asrc = g_A0 + (size_t)bm * IN_DIM;
        const __nv_bfloat16* Bsrc = g_B0 + (size_t)bn * IN_DIM;
        // double-buffered: [A(16K) B(8K)] x2 = 48KB
        auto stage_load = [&](int s) {
            const int buf = s & 1;
            const int k0 = s * BK;
            uint32_t sA = sb + buf * (TILE_A + TILE_BB);
            uint32_t sB = sA + TILE_A;
#pragma unroll
            for (int u = 0; u < 4; u++) {       // A: 1024 chunks
                int v = tid + 256 * u;
                int row = v >> 3;
                int c = (v & 7) * 16;
                const void* g = (const char*)(Asrc + (size_t)row * IN_DIM + k0) + c;
                asm volatile("cp.async.cg.shared.global [%0], [%1], 16;"
                             :: "r"(sA + SW128(row * 128 + c)), "l"(g));
            }
#pragma unroll
            for (int u = 0; u < 2; u++) {       // B: 512 chunks
                int v = tid + 256 * u;
                int row = v >> 3;
                int c = (v & 7) * 16;
                const void* g = (const char*)(Bsrc + (size_t)row * IN_DIM + k0) + c;
                asm volatile("cp.async.cg.shared.global [%0], [%1], 16;"
                             :: "r"(sB + SW128(row * 128 + c)), "l"(g));
            }
            asm volatile("cp.async.commit_group;" ::: "memory");
        };

        float hi[2][4][4], lo[2][4][4];
#pragma unroll
        for (int mt = 0; mt < 2; mt++)
#pragma unroll
            for (int nf = 0; nf < 4; nf++)
#pragma unroll
                for (int j = 0; j < 4; j++) { hi[mt][nf][j] = 0.0f; lo[mt][nf][j] = 0.0f; }

        stage_load(0);

        for (int s = 0; s < NST; s++) {
            if (s + 1 < NST) {
                stage_load(s + 1);
                asm volatile("cp.async.wait_group 1;" ::: "memory");
            } else {
                asm volatile("cp.async.wait_group 0;" ::: "memory");
            }
            __syncthreads();

            const uint32_t sA = sb + (s & 1) * (TILE_A + TILE_BB);
            const uint32_t sB = sA + TILE_A;

            float tmp[2][4][4];
#pragma unroll
            for (int j = 0; j < 4; j++) {       // chain-4 over 4 k16 steps
                uint32_t af[2][4];
                uint32_t bfr[2][4];
                int kb_a = j * 32 + (mi >> 1) * 16;
                int kb_b = j * 32 + (mi & 1) * 16;
#pragma unroll
                for (int mt = 0; mt < 2; mt++) {
                    int row = warp_m * 32 + mt * 16 + (mi & 1) * 8 + r8;
                    ldmx4(af[mt], sA + SW128(row * 128 + kb_a));
                }
#pragma unroll
                for (int np = 0; np < 2; np++) {
                    int n = warp_n * 32 + np * 16 + (mi >> 1) * 8 + r8;
                    ldmx4(bfr[np], sB + SW128(n * 128 + kb_b));
                }
                if (j == 0) {
#pragma unroll
                    for (int mt = 0; mt < 2; mt++)
#pragma unroll
                        for (int nf = 0; nf < 4; nf++)
                            mma16816_z(tmp[mt][nf], af[mt], &bfr[nf >> 1][(nf & 1) * 2]);
                } else {
#pragma unroll
                    for (int mt = 0; mt < 2; mt++)
#pragma unroll
                        for (int nf = 0; nf < 4; nf++)
                            mma16816(tmp[mt][nf], af[mt], &bfr[nf >> 1][(nf & 1) * 2]);
                }
            }
#pragma unroll
            for (int mt = 0; mt < 2; mt++)
#pragma unroll
                for (int nf = 0; nf < 4; nf++)
#pragma unroll
                    for (int j = 0; j < 4; j++)
                        lo[mt][nf][j] = __fadd_rn(lo[mt][nf][j], tmp[mt][nf][j]);

            if ((s & 3) == 3) {                 // flush lo -> hi every 4 ktiles
#pragma unroll
                for (int mt = 0; mt < 2; mt++)
#pragma unroll
                    for (int nf = 0; nf < 4; nf++)
#pragma unroll
                        for (int j = 0; j < 4; j++) {
                            hi[mt][nf][j] = __fadd_rn(hi[mt][nf][j], lo[mt][nf][j]);
                            lo[mt][nf][j] = 0.0f;
                        }
            }
            __syncthreads();
        }

        // epilogue: hi + bias -> g_cur
#pragma unroll
        for (int mt = 0; mt < 2; mt++)
#pragma unroll
            for (int h = 0; h < 2; h++) {
                int row = bm + warp_m * 32 + mt * 16 + h * 8 + qr;
                float* dst = g_cur + (size_t)row * OUT_DIM + bn + warp_n * 32 + qc;
                const float* bp = bias + bn + warp_n * 32 + qc;
#pragma unroll
                for (int nf = 0; nf < 4; nf++) {
                    float2 v;
                    v.x = __fadd_rn(hi[mt][nf][h*2+0], bp[nf*8+0]);
                    v.y = __fadd_rn(hi[mt][nf][h*2+1], bp[nf*8+1]);
                    *reinterpret_cast<float2*>(dst + nf * 8) = v;
                }
            }
    } else {
        // ============== small path: 5 split-combos -> g_cur2 ===============
        const __nv_bfloat16* srcA[3] = {
            g_A0 + (size_t)bm * IN_DIM, g_A1 + (size_t)bm * IN_DIM,
            g_A2 + (size_t)bm * IN_DIM };
        const __nv_bfloat16* srcB[3] = {
            g_B0 + (size_t)bn * IN_DIM, g_B1 + (size_t)bn * IN_DIM,
            g_B2 + (size_t)bn * IN_DIM };

        auto stage_load = [&](int s) {
            const int k0 = s * BK;
#pragma unroll
            for (int t = 0; t < 3; t++) {       // A tiles: 128 rows
                const __nv_bfloat16* base = srcA[t] + k0;
                uint32_t stile = sb + t * TILE_A;
#pragma unroll
                for (int u = 0; u < 4; u++) {
                    int v = tid + 256 * u;
                    int row = v >> 3;
                    int c = (v & 7) * 16;
                    const void* g = (const char*)(base + (size_t)row * IN_DIM) + c;
                    asm volatile("cp.async.cg.shared.global [%0], [%1], 16;"
                                 :: "r"(stile + SW128(row * 128 + c)), "l"(g));
                }
            }
#pragma unroll
            for (int t = 0; t < 3; t++) {       // B tiles: 64 rows
                const __nv_bfloat16* base = srcB[t] + k0;
                uint32_t stile = sb + 3 * TILE_A + t * TILE_BB;
#pragma unroll
                for (int u = 0; u < 2; u++) {
                    int v = tid + 256 * u;
                    int row = v >> 3;
                    int c = (v & 7) * 16;
                    const void* g = (const char*)(base + (size_t)row * IN_DIM) + c;
                    asm volatile("cp.async.cg.shared.global [%0], [%1], 16;"
                                 :: "r"(stile + SW128(row * 128 + c)), "l"(g));
                }
            }
            asm volatile("cp.async.commit_group;" ::: "memory");
        };

        float accs[2][4][4];
#pragma unroll
        for (int mt = 0; mt < 2; mt++)
#pragma unroll
            for (int nf = 0; nf < 4; nf++)
#pragma unroll
                for (int j = 0; j < 4; j++) accs[mt][nf][j] = 0.0f;

        stage_load(0);

        for (int s = 0; s < NST; s++) {
            asm volatile("cp.async.wait_group 0;" ::: "memory");
            __syncthreads();

#pragma unroll
            for (int ks = 0; ks < 4; ks++) {
                const int kb_a = ks * 32 + (mi >> 1) * 16;
                const int kb_b = ks * 32 + (mi & 1) * 16;
                // full set: b0:{a1,a2}, b1:{a0,a1}, b2:{a0}
                constexpr int NA[3]    = {2, 2, 1};
                constexpr int AI[3][2] = {{1, 2}, {0, 1}, {0, 0}};
#pragma unroll
                for (int bsp = 0; bsp < 3; bsp++) {
                    uint32_t bfr[2][4];
#pragma unroll
                    for (int np = 0; np < 2; np++) {
                        int n = warp_n * 32 + np * 16 + (mi >> 1) * 8 + r8;
                        ldmx4(bfr[np], sb + 3 * TILE_A + bsp * TILE_BB +
                                       SW128(n * 128 + kb_b));
                    }
#pragma unroll
                    for (int ai = 0; ai < 2; ai++) {
                        if (ai < NA[bsp]) {
                            uint32_t af[2][4];
#pragma unroll
                            for (int mt = 0; mt < 2; mt++) {
                                int row = warp_m * 32 + mt * 16 + (mi & 1) * 8 + r8;
                                ldmx4(af[mt], sb + AI[bsp][ai] * TILE_A +
                                              SW128(row * 128 + kb_a));
                            }
#pragma unroll
                            for (int mt = 0; mt < 2; mt++)
#pragma unroll
                                for (int nf = 0; nf < 4; nf++)
                                    mma16816(accs[mt][nf], af[mt],
                                             &bfr[nf >> 1][(nf & 1) * 2]);
                        }
                    }
                }
            }
            __syncthreads();                    // WAR before reload
            if (s + 1 < NST) stage_load(s + 1);
        }

        // epilogue: smalls -> g_cur2 (pure store)
#pragma unroll
        for (int mt = 0; mt < 2; mt++)
#pragma unroll
            for (int h = 0; h < 2; h++) {
                int row = bm + warp_m * 32 + mt * 16 + h * 8 + qr;
                float* dst = g_cur2 + (size_t)row * OUT_DIM + bn + warp_n * 32 + qc;
#pragma unroll
                for (int nf = 0; nf < 4; nf++) {
                    float2 v;
                    v.x = accs[mt][nf][h*2+0];
                    v.y = accs[mt][nf][h*2+1];
                    *reinterpret_cast<float2*>(dst + nf * 8) = v;
                }
            }
    }
}

// ------------------------------ LIF scan -----------------------------------
__global__ __launch_bounds__(256) void lif_scan_kernel(float* __restrict__ out)
{
    const int idx = blockIdx.x * blockDim.x + threadIdx.x;
    const int BO  = B_DIM * OUT_DIM;
    float mem = 0.0f;
#pragma unroll
    for (int t = 0; t < T_DIM; t++) {
        // same rounding order as before: (main+bias) + smalls
        float c = __fadd_rn(g_cur[(size_t)t * BO + idx], g_cur2[(size_t)t * BO + idx]);
        mem = __fadd_rn(__fmul_rn(mem, DECAY_V), c);
        float spk = (__fadd_rn(mem, -THR_V) > 0.0f) ? 1.0f : 0.0f;
        mem = __fadd_rn(mem, -spk * THR_V);
        out[(size_t)t * BO + idx] = spk;
    }
}

// ---------------------------------------------------------------------------
extern "C" void kernel_launch(void* const* d_in, const int* in_sizes, int n_in,
                              void* d_out, int out_size)
{
    const float* x = (const float*)d_in[0];
    const float* W = (const float*)d_in[1];
    const float* b = (const float*)d_in[2];
    float* out = (float*)d_out;

    split_x_kernel<<<(M_DIM * (size_t)IN_DIM / 4) / 256, 256>>>(x);
    split_w_kernel<<<(OUT_DIM * (size_t)IN_DIM / 4) / 256, 256>>>(W);

    cudaFuncSetAttribute(gemm_fused_kernel,
                         cudaFuncAttributeMaxDynamicSharedMemorySize, F_SMEM);
    dim3 grid(2 * OUT_DIM / BN, M_DIM / BM);  // (64, 64): alternating kinds
    gemm_fused_kernel<<<grid, 256, F_SMEM>>>(b);

    lif_scan_kernel<<<(B_DIM * OUT_DIM) / 256, 256>>>(out);
}

// round 13
// speedup vs baseline: 1.0873x; 1.0873x over previous
#include <cuda_runtime.h>
#include <cuda_bf16.h>
#include <cstdint>

// ---------------------------------------------------------------------------
// LIF layer: cur = X @ W^T + b via bf16x3-split GEMM on mma.sync (HMMA).
// R13: revert R12's fused-kernel experiment (tail imbalance + extra traffic).
//      K2 = R11's proven kernel (BN=64, 3 CTAs/SM, 687us @ 83% tensor).
//      K1 reshaped to the same proven geometry: BN=64, 256 threads,
//      48KB double-buffered smem, 2 CTAs/SM.
// ---------------------------------------------------------------------------

constexpr int T_DIM  = 64;
constexpr int B_DIM  = 128;
constexpr int IN_DIM = 2048;
constexpr int OUT_DIM = 2048;
constexpr int M_DIM  = T_DIM * B_DIM;          // 8192
constexpr float THR_V   = 1.0f;
constexpr float DECAY_V = 0.60653065971263342f; // exp(-1/2) rounded to fp32

// ------------------------------ scratch -----------------------------------
__device__ float g_cur[(size_t)M_DIM * OUT_DIM];                 // 64 MB
__device__ __nv_bfloat16 g_A0[(size_t)M_DIM * IN_DIM];           // 32 MB each
__device__ __nv_bfloat16 g_A1[(size_t)M_DIM * IN_DIM];
__device__ __nv_bfloat16 g_A2[(size_t)M_DIM * IN_DIM];
__device__ __nv_bfloat16 g_B0[(size_t)OUT_DIM * IN_DIM];         // 8 MB each
__device__ __nv_bfloat16 g_B1[(size_t)OUT_DIM * IN_DIM];
__device__ __nv_bfloat16 g_B2[(size_t)OUT_DIM * IN_DIM];

// ------------------------------ helpers -----------------------------------
__device__ __forceinline__ uint32_t smem_u32(const void* p) {
    uint32_t a;
    asm("{ .reg .u64 t; cvta.to.shared.u64 t, %1; cvt.u32.u64 %0, t; }"
        : "=r"(a) : "l"(p));
    return a;
}

#define SW128(o) ((o) ^ (((o) >> 3) & 0x70))

__device__ __forceinline__ void ldmx4(uint32_t* r, uint32_t addr) {
    asm volatile("ldmatrix.sync.aligned.m8n8.x4.shared.b16 {%0,%1,%2,%3}, [%4];"
                 : "=r"(r[0]), "=r"(r[1]), "=r"(r[2]), "=r"(r[3]) : "r"(addr));
}
// chained accumulate: d += a*b
__device__ __forceinline__ void mma16816(float* d, const uint32_t* a,
                                         const uint32_t* b) {
    asm volatile(
        "mma.sync.aligned.m16n8k16.row.col.f32.bf16.bf16.f32 "
        "{%0,%1,%2,%3}, {%4,%5,%6,%7}, {%8,%9}, {%0,%1,%2,%3};"
        : "+f"(d[0]), "+f"(d[1]), "+f"(d[2]), "+f"(d[3])
        : "r"(a[0]), "r"(a[1]), "r"(a[2]), "r"(a[3]), "r"(b[0]), "r"(b[1]));
}
// zero-C form: d = a*b
__device__ __forceinline__ void mma16816_z(float* d, const uint32_t* a,
                                           const uint32_t* b) {
    asm volatile(
        "mma.sync.aligned.m16n8k16.row.col.f32.bf16.bf16.f32 "
        "{%0,%1,%2,%3}, {%4,%5,%6,%7}, {%8,%9}, {%10,%11,%12,%13};"
        : "=f"(d[0]), "=f"(d[1]), "=f"(d[2]), "=f"(d[3])
        : "r"(a[0]), "r"(a[1]), "r"(a[2]), "r"(a[3]), "r"(b[0]), "r"(b[1]),
          "f"(0.0f), "f"(0.0f), "f"(0.0f), "f"(0.0f));
}

// ------------------------- split fp32 -> 3x bf16 ---------------------------
__device__ __forceinline__ void split3(float v, __nv_bfloat16& h0,
                                       __nv_bfloat16& h1, __nv_bfloat16& h2) {
    h0 = __float2bfloat16(v);
    float r1 = v - __bfloat162float(h0);
    h1 = __float2bfloat16(r1);
    float r2 = r1 - __bfloat162float(h1);
    h2 = __float2bfloat16(r2);
}

__global__ __launch_bounds__(256) void split_x_kernel(const float* __restrict__ src)
{
    int i = blockIdx.x * blockDim.x + threadIdx.x;
    float4 a = reinterpret_cast<const float4*>(src)[i];
    float v[4] = {a.x, a.y, a.z, a.w};
    __nv_bfloat16 h0[4], h1[4], h2[4];
#pragma unroll
    for (int j = 0; j < 4; j++) split3(v[j], h0[j], h1[j], h2[j]);
    __nv_bfloat162 p;
    p = {h0[0], h0[1]}; reinterpret_cast<__nv_bfloat162*>(g_A0)[2*i  ] = p;
    p = {h0[2], h0[3]}; reinterpret_cast<__nv_bfloat162*>(g_A0)[2*i+1] = p;
    p = {h1[0], h1[1]}; reinterpret_cast<__nv_bfloat162*>(g_A1)[2*i  ] = p;
    p = {h1[2], h1[3]}; reinterpret_cast<__nv_bfloat162*>(g_A1)[2*i+1] = p;
    p = {h2[0], h2[1]}; reinterpret_cast<__nv_bfloat162*>(g_A2)[2*i  ] = p;
    p = {h2[2], h2[3]}; reinterpret_cast<__nv_bfloat162*>(g_A2)[2*i+1] = p;
}

__global__ __launch_bounds__(256) void split_w_kernel(const float* __restrict__ src)
{
    int i = blockIdx.x * blockDim.x + threadIdx.x;
    float4 a = reinterpret_cast<const float4*>(src)[i];
    float v[4] = {a.x, a.y, a.z, a.w};
    __nv_bfloat16 h0[4], h1[4], h2[4];
#pragma unroll
    for (int j = 0; j < 4; j++) split3(v[j], h0[j], h1[j], h2[j]);
    __nv_bfloat162 p;
    p = {h0[0], h0[1]}; reinterpret_cast<__nv_bfloat162*>(g_B0)[2*i  ] = p;
    p = {h0[2], h0[3]}; reinterpret_cast<__nv_bfloat162*>(g_B0)[2*i+1] = p;
    p = {h1[0], h1[1]}; reinterpret_cast<__nv_bfloat162*>(g_B1)[2*i  ] = p;
    p = {h1[2], h1[3]}; reinterpret_cast<__nv_bfloat162*>(g_B1)[2*i+1] = p;
    p = {h2[0], h2[1]}; reinterpret_cast<__nv_bfloat162*>(g_B2)[2*i  ] = p;
    p = {h2[2], h2[3]}; reinterpret_cast<__nv_bfloat162*>(g_B2)[2*i+1] = p;
}

// ------------------------------ common dims --------------------------------
constexpr int BM = 128, BN = 64, BK = 64;
constexpr int NST = IN_DIM / BK;              // 32 ktiles
constexpr int TILE_A  = 128 * 128;            // 16 KB A tile (128 rows)
constexpr int TILE_BB = 64 * 128;             // 8 KB B tile (64 rows)

// ============================ K1: main a0*b0 ================================
// BN=64: 256 threads = 8 warps (4 wm x 2 wn), warp tile 32x32.
// Double-buffered [A(16K)+B(8K)]x2 = 48 KB -> 2 CTAs/SM.
// Drain: chain-4 TC per ktile -> lo (plain FADD), lo -> hi every 4 ktiles.
constexpr int K1_SMEM = 2 * (TILE_A + TILE_BB);   // 49152

__global__ __launch_bounds__(256, 2)
void gemm_main_kernel(const float* __restrict__ bias)
{
    extern __shared__ char smem[];
    const uint32_t sb = smem_u32(smem);
    const int tid  = threadIdx.x;
    const int wid  = tid >> 5;
    const int lane = tid & 31;
    const int bm = blockIdx.y * BM;
    const int bn = blockIdx.x * BN;
    const int warp_m = wid & 3;
    const int warp_n = wid >> 2;
    const int mi = lane >> 3, r8 = lane & 7;

    const __nv_bfloat16* Asrc = g_A0 + (size_t)bm * IN_DIM;
    const __nv_bfloat16* Bsrc = g_B0 + (size_t)bn * IN_DIM;

    auto stage_load = [&](int s) {
        const int buf = s & 1;
        const int k0 = s * BK;
        uint32_t sA = sb + buf * (TILE_A + TILE_BB);
        uint32_t sB = sA + TILE_A;
#pragma unroll
        for (int u = 0; u < 4; u++) {           // A: 1024 16B chunks
            int v = tid + 256 * u;
            int row = v >> 3;
            int c = (v & 7) * 16;
            const void* g = (const char*)(Asrc + (size_t)row * IN_DIM + k0) + c;
            asm volatile("cp.async.cg.shared.global [%0], [%1], 16;"
                         :: "r"(sA + SW128(row * 128 + c)), "l"(g));
        }
#pragma unroll
        for (int u = 0; u < 2; u++) {           // B: 512 16B chunks
            int v = tid + 256 * u;
            int row = v >> 3;
            int c = (v & 7) * 16;
            const void* g = (const char*)(Bsrc + (size_t)row * IN_DIM + k0) + c;
            asm volatile("cp.async.cg.shared.global [%0], [%1], 16;"
                         :: "r"(sB + SW128(row * 128 + c)), "l"(g));
        }
        asm volatile("cp.async.commit_group;" ::: "memory");
    };

    float hi[2][4][4], lo[2][4][4];
#pragma unroll
    for (int mt = 0; mt < 2; mt++)
#pragma unroll
        for (int nf = 0; nf < 4; nf++)
#pragma unroll
            for (int j = 0; j < 4; j++) { hi[mt][nf][j] = 0.0f; lo[mt][nf][j] = 0.0f; }

    stage_load(0);

    for (int s = 0; s < NST; s++) {
        if (s + 1 < NST) {
            stage_load(s + 1);
            asm volatile("cp.async.wait_group 1;" ::: "memory");
        } else {
            asm volatile("cp.async.wait_group 0;" ::: "memory");
        }
        __syncthreads();

        const uint32_t sA = sb + (s & 1) * (TILE_A + TILE_BB);
        const uint32_t sB = sA + TILE_A;

        // one chain-4 group per ktile
        float tmp[2][4][4];
#pragma unroll
        for (int j = 0; j < 4; j++) {
            uint32_t af[2][4];
            uint32_t bfr[2][4];
            int kb_a = j * 32 + (mi >> 1) * 16;
            int kb_b = j * 32 + (mi & 1) * 16;
#pragma unroll
            for (int mt = 0; mt < 2; mt++) {
                int row = warp_m * 32 + mt * 16 + (mi & 1) * 8 + r8;
                ldmx4(af[mt], sA + SW128(row * 128 + kb_a));
            }
#pragma unroll
            for (int np = 0; np < 2; np++) {
                int n = warp_n * 32 + np * 16 + (mi >> 1) * 8 + r8;
                ldmx4(bfr[np], sB + SW128(n * 128 + kb_b));
            }
            if (j == 0) {
#pragma unroll
                for (int mt = 0; mt < 2; mt++)
#pragma unroll
                    for (int nf = 0; nf < 4; nf++)
                        mma16816_z(tmp[mt][nf], af[mt], &bfr[nf >> 1][(nf & 1) * 2]);
            } else {
#pragma unroll
                for (int mt = 0; mt < 2; mt++)
#pragma unroll
                    for (int nf = 0; nf < 4; nf++)
                        mma16816(tmp[mt][nf], af[mt], &bfr[nf >> 1][(nf & 1) * 2]);
            }
        }
#pragma unroll
        for (int mt = 0; mt < 2; mt++)
#pragma unroll
            for (int nf = 0; nf < 4; nf++)
#pragma unroll
                for (int j = 0; j < 4; j++)
                    lo[mt][nf][j] = __fadd_rn(lo[mt][nf][j], tmp[mt][nf][j]);

        if ((s & 3) == 3) {                     // flush lo -> hi every 4 ktiles
#pragma unroll
            for (int mt = 0; mt < 2; mt++)
#pragma unroll
                for (int nf = 0; nf < 4; nf++)
#pragma unroll
                    for (int j = 0; j < 4; j++) {
                        hi[mt][nf][j] = __fadd_rn(hi[mt][nf][j], lo[mt][nf][j]);
                        lo[mt][nf][j] = 0.0f;
                    }
        }
        __syncthreads();
    }

    // Epilogue: hi + bias -> g_cur
    const int qr = lane >> 2;
    const int qc = (lane & 3) * 2;
#pragma unroll
    for (int mt = 0; mt < 2; mt++)
#pragma unroll
        for (int h = 0; h < 2; h++) {
            int row = bm + warp_m * 32 + mt * 16 + h * 8 + qr;
            float* dst = g_cur + (size_t)row * OUT_DIM + bn + warp_n * 32 + qc;
            const float* bp = bias + bn + warp_n * 32 + qc;
#pragma unroll
            for (int nf = 0; nf < 4; nf++) {
                float2 v;
                v.x = __fadd_rn(hi[mt][nf][h*2+0], bp[nf*8+0]);
                v.y = __fadd_rn(hi[mt][nf][h*2+1], bp[nf*8+1]);
                *reinterpret_cast<float2*>(dst + nf * 8) = v;
            }
        }
}

// ====================== K2: 5 small split-combos ============================
// R11's proven kernel: BN=64, 256 threads = 8 warps (4 wm x 2 wn), warp tile
// 32x32, 72KB single-buffered smem, 3 CTAs/SM.
// Products (full set): a1*b0, a2*b0, a0*b1, a1*b1, a0*b2.
constexpr int K2_SMEM = 3 * TILE_A + 3 * TILE_BB;  // 73728

__global__ __launch_bounds__(256, 3)
void gemm_small_kernel()
{
    extern __shared__ char smem[];
    const uint32_t sb = smem_u32(smem);
    const int tid  = threadIdx.x;
    const int wid  = tid >> 5;
    const int lane = tid & 31;
    const int bm = blockIdx.y * BM;
    const int bn = blockIdx.x * BN;
    const int warp_m = wid & 3;      // 0..3
    const int warp_n = wid >> 2;     // 0..1

    const __nv_bfloat16* srcA[3] = {
        g_A0 + (size_t)bm * IN_DIM, g_A1 + (size_t)bm * IN_DIM,
        g_A2 + (size_t)bm * IN_DIM };
    const __nv_bfloat16* srcB[3] = {
        g_B0 + (size_t)bn * IN_DIM, g_B1 + (size_t)bn * IN_DIM,
        g_B2 + (size_t)bn * IN_DIM };

    auto stage_load = [&](int s) {
        const int k0 = s * BK;
#pragma unroll
        for (int t = 0; t < 3; t++) {           // A tiles: 128 rows
            const __nv_bfloat16* base = srcA[t] + k0;
            uint32_t stile = sb + t * TILE_A;
#pragma unroll
            for (int u = 0; u < 4; u++) {
                int v = tid + 256 * u;
                int row = v >> 3;
                int c = (v & 7) * 16;
                const void* g = (const char*)(base + (size_t)row * IN_DIM) + c;
                asm volatile("cp.async.cg.shared.global [%0], [%1], 16;"
                             :: "r"(stile + SW128(row * 128 + c)), "l"(g));
            }
        }
#pragma unroll
        for (int t = 0; t < 3; t++) {           // B tiles: 64 rows
            const __nv_bfloat16* base = srcB[t] + k0;
            uint32_t stile = sb + 3 * TILE_A + t * TILE_BB;
#pragma unroll
            for (int u = 0; u < 2; u++) {
                int v = tid + 256 * u;
                int row = v >> 3;
                int c = (v & 7) * 16;
                const void* g = (const char*)(base + (size_t)row * IN_DIM) + c;
                asm volatile("cp.async.cg.shared.global [%0], [%1], 16;"
                             :: "r"(stile + SW128(row * 128 + c)), "l"(g));
            }
        }
        asm volatile("cp.async.commit_group;" ::: "memory");
    };

    float accs[2][4][4];
#pragma unroll
    for (int mt = 0; mt < 2; mt++)
#pragma unroll
        for (int nf = 0; nf < 4; nf++)
#pragma unroll
            for (int j = 0; j < 4; j++) accs[mt][nf][j] = 0.0f;

    const int mi = lane >> 3, r8 = lane & 7;

    stage_load(0);

    for (int s = 0; s < NST; s++) {
        asm volatile("cp.async.wait_group 0;" ::: "memory");
        __syncthreads();

#pragma unroll
        for (int ks = 0; ks < 4; ks++) {
            const int kb_a = ks * 32 + (mi >> 1) * 16;
            const int kb_b = ks * 32 + (mi & 1) * 16;
            // full product set: b0:{a1,a2}, b1:{a0,a1}, b2:{a0}
            constexpr int NA[3]    = {2, 2, 1};
            constexpr int AI[3][2] = {{1, 2}, {0, 1}, {0, 0}};
#pragma unroll
            for (int bsp = 0; bsp < 3; bsp++) {
                uint32_t bfr[2][4];
#pragma unroll
                for (int np = 0; np < 2; np++) {
                    int n = warp_n * 32 + np * 16 + (mi >> 1) * 8 + r8;
                    ldmx4(bfr[np], sb + 3 * TILE_A + bsp * TILE_BB +
                                   SW128(n * 128 + kb_b));
                }
#pragma unroll
                for (int ai = 0; ai < 2; ai++) {
                    if (ai < NA[bsp]) {
                        uint32_t af[2][4];
#pragma unroll
                        for (int mt = 0; mt < 2; mt++) {
                            int row = warp_m * 32 + mt * 16 + (mi & 1) * 8 + r8;
                            ldmx4(af[mt], sb + AI[bsp][ai] * TILE_A +
                                          SW128(row * 128 + kb_a));
                        }
#pragma unroll
                        for (int mt = 0; mt < 2; mt++)
#pragma unroll
                            for (int nf = 0; nf < 4; nf++)
                                mma16816(accs[mt][nf], af[mt],
                                         &bfr[nf >> 1][(nf & 1) * 2]);
                    }
                }
            }
        }
        __syncthreads();                        // WAR: compute done before reload
        if (s + 1 < NST) stage_load(s + 1);
    }

    // Epilogue: g_cur += smalls
    const int qr = lane >> 2;
    const int qc = (lane & 3) * 2;
#pragma unroll
    for (int mt = 0; mt < 2; mt++)
#pragma unroll
        for (int h = 0; h < 2; h++) {
            int row = bm + warp_m * 32 + mt * 16 + h * 8 + qr;
            float* dst = g_cur + (size_t)row * OUT_DIM + bn + warp_n * 32 + qc;
#pragma unroll
            for (int nf = 0; nf < 4; nf++) {
                float2 v = *reinterpret_cast<float2*>(dst + nf * 8);
                v.x = __fadd_rn(v.x, accs[mt][nf][h*2+0]);
                v.y = __fadd_rn(v.y, accs[mt][nf][h*2+1]);
                *reinterpret_cast<float2*>(dst + nf * 8) = v;
            }
        }
}

// ------------------------------ LIF scan -----------------------------------
__global__ __launch_bounds__(256) void lif_scan_kernel(float* __restrict__ out)
{
    const int idx = blockIdx.x * blockDim.x + threadIdx.x;
    const int BO  = B_DIM * OUT_DIM;
    float mem = 0.0f;
#pragma unroll
    for (int t = 0; t < T_DIM; t++) {
        float c = g_cur[(size_t)t * BO + idx];
        mem = __fadd_rn(__fmul_rn(mem, DECAY_V), c);
        float spk = (__fadd_rn(mem, -THR_V) > 0.0f) ? 1.0f : 0.0f;
        mem = __fadd_rn(mem, -spk * THR_V);
        out[(size_t)t * BO + idx] = spk;
    }
}

// ---------------------------------------------------------------------------
extern "C" void kernel_launch(void* const* d_in, const int* in_sizes, int n_in,
                              void* d_out, int out_size)
{
    const float* x = (const float*)d_in[0];
    const float* W = (const float*)d_in[1];
    const float* b = (const float*)d_in[2];
    float* out = (float*)d_out;

    split_x_kernel<<<(M_DIM * (size_t)IN_DIM / 4) / 256, 256>>>(x);
    split_w_kernel<<<(OUT_DIM * (size_t)IN_DIM / 4) / 256, 256>>>(W);

    dim3 grid(OUT_DIM / BN, M_DIM / BM);      // (32, 64)

    cudaFuncSetAttribute(gemm_main_kernel,
                         cudaFuncAttributeMaxDynamicSharedMemorySize, K1_SMEM);
    gemm_main_kernel<<<grid, 256, K1_SMEM>>>(b);

    cudaFuncSetAttribute(gemm_small_kernel,
                         cudaFuncAttributeMaxDynamicSharedMemorySize, K2_SMEM);
    gemm_small_kernel<<<grid, 256, K2_SMEM>>>();

    lif_scan_kernel<<<(B_DIM * OUT_DIM) / 256, 256>>>(out);
}